// round 9
// baseline (speedup 1.0000x reference)
#include <cuda_runtime.h>
#include <cuda_bf16.h>
#include <cstdint>

#define NN      202500
#define K_PRE   6000
#define K_POST  300
#define NWRD    94
#define CAP     16384
#define NB      148
#define TPB     512
#define TOT     (NB*TPB)
#define IOU_TH  0.7f
#define MIN_SZ  0.016f
#define W1      1024            // window candidates
#define WW      16              // window words
#define NSTRIPR 12
#define FCOL    (NWRD - WW)

typedef unsigned long long u64;
typedef unsigned int u32;

__device__ u64    g_keys[NN];
__device__ float4 g_boxes[NN];
__device__ u32    g_hist[65536];     // zeroed at end of k_D (and statically)
__device__ u32    g_bcnt[65536];
__device__ u32    g_suf[65537];
__device__ u32    g_thresh;
__device__ u64    g_cand[CAP];
__device__ float4 g_sbox[K_PRE];
__device__ u64    g_valid[NWRD];
__device__ u64    g_wsupp[W1 * WW];
__device__ u64    g_supp[(size_t)K_PRE * NWRD];
__device__ u32    g_bar[8];          // generation counters (never reset)
__device__ int    g_fb;
__device__ int    g_cnt;
__device__ int    g_klist[K_POST];

extern __shared__ u64 s_dyn[];       // 128KB where used

// ===================== k_A: decode + keys + histogram =====================
__global__ void __launch_bounds__(TPB, 1)
k_A(const float2* __restrict__ cls,
    const float4* __restrict__ loc,
    const float4* __restrict__ anc) {
    const int flat = blockIdx.x * TPB + threadIdx.x;
    if (flat < NWRD) g_valid[flat] = 0ull;
    for (int n = flat; n < NN; n += TOT) {
        float2 c = cls[n];
        float m  = fmaxf(c.x, c.y);
        float e0 = expf(c.x - m);
        float e1 = expf(c.y - m);
        float s  = __fdiv_rn(e1, e0 + e1);

        float4 A = anc[n];
        float pcx = (A.z + A.x) * 0.5f;
        float pcy = (A.w + A.y) * 0.5f;
        float pw  = A.z - A.x;
        float ph  = A.w - A.y;

        float4 L = loc[n];
        float cx = L.x * pw + pcx;
        float cy = L.y * ph + pcy;
        float w  = expf(L.z) * pw;
        float h  = expf(L.w) * ph;

        float X0 = fminf(fmaxf(cx - w * 0.5f, 0.0f), 1.0f);
        float Y0 = fminf(fmaxf(cy - h * 0.5f, 0.0f), 1.0f);
        float X1 = fminf(fmaxf(cx + w * 0.5f, 0.0f), 1.0f);
        float Y1 = fminf(fmaxf(cy + h * 0.5f, 0.0f), 1.0f);

        bool valid = ((X1 - X0) >= MIN_SZ) && ((Y1 - Y0) >= MIN_SZ);
        float sm = valid ? s : -1.0f;

        u32 b  = __float_as_uint(sm);
        u32 fk = b ^ ((b >> 31) ? 0xFFFFFFFFu : 0x80000000u);

        g_keys[n]  = ((u64)fk << 32) | (u32)(~(u32)n);
        g_boxes[n] = make_float4(X0, Y0, X1, Y1);
        atomicAdd(&g_hist[fk >> 16], 1u);
    }
}

// ===================== k_B: suffix sums + threshold (1 block) =====================
__global__ void __launch_bounds__(1024, 1)
k_B() {
    __shared__ u32 s_wt[32];
    const int tid  = threadIdx.x;
    const int lane = tid & 31;
    const int wid  = tid >> 5;
    u32 ssum = 0;
    #pragma unroll 16
    for (int b = 0; b < 64; b++) ssum += g_hist[tid * 64 + b];
    u32 v = ssum;
    #pragma unroll
    for (int d = 1; d < 32; d <<= 1) {
        u32 o = __shfl_down_sync(0xFFFFFFFFu, v, d);
        if (lane < 32 - d) v += o;
    }
    if (lane == 0) s_wt[wid] = v;
    __syncthreads();
    if (tid < 32) {
        u32 t = s_wt[tid];
        #pragma unroll
        for (int d = 1; d < 32; d <<= 1) {
            u32 o = __shfl_down_sync(0xFFFFFFFFu, t, d);
            if (tid < 32 - d) t += o;
        }
        s_wt[tid] = t;
    }
    __syncthreads();
    u32 above = (wid < 31) ? s_wt[wid + 1] : 0u;
    u32 acc = (v + above) - ssum;
    #pragma unroll 8
    for (int b = 63; b >= 0; b--) {
        int idx = tid * 64 + b;
        u32 prev = acc;
        acc += g_hist[idx];
        g_suf[idx] = acc;
        if (prev < (u32)K_PRE && acc >= (u32)K_PRE) g_thresh = (u32)idx;
    }
}

// ===================== k_C: compact into per-bucket regions =====================
__global__ void __launch_bounds__(TPB, 1)
k_C() {
    const int flat = blockIdx.x * TPB + threadIdx.x;
    u32 thr = g_thresh;
    for (int n = flat; n < NN; n += TOT) {
        u64 k = g_keys[n];
        u32 b = (u32)(k >> 48);
        if (b >= thr) {
            u32 pos = g_suf[b + 1] + atomicAdd(&g_bcnt[b], 1u);
            if (pos < CAP) g_cand[pos] = k;
        }
    }
}

// ===================== k_D: rank via smem-staged keys; zero hist/bcnt =====================
// IDEMPOTENT: safe to run twice.
__global__ void __launch_bounds__(TPB, 1)
k_D() {
    const int tid  = threadIdx.x;
    const int flat = blockIdx.x * TPB + tid;
    u32 thr = g_thresh;
    u32 M = g_suf[thr]; if (M > CAP) M = CAP;
    for (u32 t = (u32)tid; t < M; t += TPB) s_dyn[t] = __ldcg(&g_cand[t]);
    __syncthreads();
    u32 i = (u32)flat;
    if (i < M) {
        u64 key = s_dyn[i];
        u32 b = (u32)(key >> 48);
        u32 start = g_suf[b + 1];
        u32 end   = g_suf[b]; if (end > M) end = M;
        u32 rank = start;
        #pragma unroll 8
        for (u32 j = start; j < end; j++) rank += (s_dyn[j] > key);
        if (rank < K_PRE) {
            u32 idx = ~(u32)key;
            g_sbox[rank] = g_boxes[idx];
            if ((u32)(key >> 32) >= 0x80000000u)
                atomicOr(&g_valid[rank >> 6], 1ull << (rank & 63));
        }
    }
    for (u32 z = (u32)flat; z < 65536u; z += TOT) { g_hist[z] = 0u; g_bcnt[z] = 0u; }
}

// ===================== k_E: window suppression matrix (128 blocks) =====================
// IDEMPOTENT: safe to run twice.
__global__ void __launch_bounds__(TPB, 1)
k_E() {
    __shared__ float4 sb[W1];
    __shared__ float  sa[W1];
    const int tid = threadIdx.x;
    for (int t = tid; t < W1; t += TPB) {
        float4 b = __ldcg(&g_sbox[t]);
        sb[t] = b;
        sa[t] = (b.z - b.x) * (b.w - b.y);
    }
    __syncthreads();

    int task = blockIdx.x * TPB + tid;      // 65536 quarter-word tasks
    int word = task >> 2;
    int i    = word >> 4;
    int c    = word & 15;
    int sub  = task & 3;
    u64 bits = 0ull;
    int iw = i >> 6;
    if (c >= iw) {
        float4 a = sb[i];
        float aarea = sa[i];
        int j0 = c * 64 + sub * 16;
        u32 lb = 0, ln = 0;
        #pragma unroll 16
        for (int jt = 0; jt < 16; jt++) {
            float4 b = sb[j0 + jt];
            float wx = fmaxf(fminf(a.z, b.z) - fmaxf(a.x, b.x), 0.0f);
            float wy = fmaxf(fminf(a.w, b.w) - fmaxf(a.y, b.y), 0.0f);
            float inter = wx * wy;
            float denom = ((aarea + sa[j0 + jt]) - inter) + 1e-12f;
            float m = IOU_TH * denom;
            lb |= ((u32)(inter > m)) << jt;
            ln |= ((u32)(fabsf(inter - m) <= 2e-6f * denom)) << jt;
        }
        while (ln) {   // rare exact fixup with reference division
            int jt = __ffs(ln) - 1; ln &= ln - 1;
            float4 b = sb[j0 + jt];
            float wx = fmaxf(fminf(a.z, b.z) - fmaxf(a.x, b.x), 0.0f);
            float wy = fmaxf(fminf(a.w, b.w) - fmaxf(a.y, b.y), 0.0f);
            float inter = wx * wy;
            float denom = ((aarea + sa[j0 + jt]) - inter) + 1e-12f;
            bool supp = __fdiv_rn(inter, denom) > IOU_TH;
            lb = (lb & ~(1u << jt)) | (((u32)supp) << jt);
        }
        bits = ((u64)lb) << (16 * sub);
    }
    bits |= __shfl_xor_sync(0xFFFFFFFFu, bits, 1);
    bits |= __shfl_xor_sync(0xFFFFFFFFu, bits, 2);
    if (sub == 0) {
        if (c == iw) {
            int bi = i & 63;
            bits &= (bi == 63) ? 0ull : (~0ull << (bi + 1));   // j > i
        }
        g_wsupp[word] = bits;
    }
}

// ===================== k_F: flattened scan (1 block) =====================
// IDEMPOTENT: safe to run twice.
__global__ void __launch_bounds__(TPB, 1)
k_F(float* __restrict__ out) {
    __shared__ int s_sel[K_POST];
    __shared__ int s_cnt;
    const int tid  = threadIdx.x;
    const int lane = tid & 31;

    u64* sc = s_dyn;
    for (int t = tid; t < W1 * WW; t += TPB) sc[t] = __ldcg(&g_wsupp[t]);
    __syncthreads();
    if (tid < 32) {
        u64 live = (lane < WW) ? __ldcg(&g_valid[lane]) : 0ull;
        int cnt = 0;
        while (cnt < K_POST) {
            u32 nz = __ballot_sync(0xFFFFFFFFu, live != 0ull);
            if (!nz) break;
            int w = __ffs(nz) - 1;
            u64 wv = __shfl_sync(0xFFFFFFFFu, live, w);
            int b = __ffsll((long long)wv) - 1;
            int i = (w << 6) + b;
            u64 row = (lane < WW) ? sc[i * WW + lane] : 0ull;
            live &= ~row;
            if (lane == w) live &= ~(1ull << b);
            if (lane == 0) s_sel[cnt] = i;
            cnt++;
        }
        if (lane == 0) s_cnt = cnt;
    }
    __syncthreads();
    int cnt = s_cnt;
    for (int k = tid; k < cnt; k += TPB) g_klist[k] = s_sel[k];
    if (cnt >= K_POST) {
        float4* out4 = reinterpret_cast<float4*>(out);
        for (int k = tid; k < K_POST; k += TPB)
            out4[k] = __ldcg(&g_sbox[s_sel[k]]);
    }
    if (tid == 0) { g_cnt = cnt; g_fb = (cnt >= K_POST) ? 0 : 1; }
}

// ===================== k_fall: continuation (guarded) =====================
__global__ void __launch_bounds__(TPB, 1)
k_fall(float* __restrict__ out) {
    __shared__ float4 s_cb[64];
    __shared__ float  s_ca[64];
    __shared__ int    s_sel[K_POST];

    const int tid  = threadIdx.x;
    const int lane = tid & 31;

    if (g_fb == 0) return;

    for (int s = blockIdx.x; s < FCOL * NSTRIPR; s += NB) {
        int c = WW + s % FCOL;
        int r = s / FCOL;
        if (c * 64 + 63 < r * TPB) continue;
        __syncthreads();
        if (tid < 64) {
            int j = c * 64 + tid;
            float4 bb = (j < K_PRE) ? __ldcg(&g_sbox[j]) : make_float4(0.f, 0.f, 0.f, 0.f);
            s_cb[tid] = bb;
            s_ca[tid] = (bb.z - bb.x) * (bb.w - bb.y);
        }
        __syncthreads();
        int i = r * TPB + tid;
        if (i < K_PRE) {
            int iw = i >> 6;
            if (c >= iw) {
                float4 a = __ldcg(&g_sbox[i]);
                float aarea = (a.z - a.x) * (a.w - a.y);
                u64 bits = 0ull, near_ = 0ull;
                #pragma unroll 8
                for (int jt = 0; jt < 64; jt++) {
                    float4 b = s_cb[jt];
                    float wx = fmaxf(fminf(a.z, b.z) - fmaxf(a.x, b.x), 0.0f);
                    float wy = fmaxf(fminf(a.w, b.w) - fmaxf(a.y, b.y), 0.0f);
                    float inter = wx * wy;
                    float denom = ((aarea + s_ca[jt]) - inter) + 1e-12f;
                    float m = IOU_TH * denom;
                    bits  |= ((u64)(inter > m)) << jt;
                    near_ |= ((u64)(fabsf(inter - m) <= 2e-6f * denom)) << jt;
                }
                while (near_) {
                    int jt = __ffsll((long long)near_) - 1; near_ &= near_ - 1;
                    float4 b = s_cb[jt];
                    float wx = fmaxf(fminf(a.z, b.z) - fmaxf(a.x, b.x), 0.0f);
                    float wy = fmaxf(fminf(a.w, b.w) - fmaxf(a.y, b.y), 0.0f);
                    float inter = wx * wy;
                    float denom = ((aarea + s_ca[jt]) - inter) + 1e-12f;
                    bool supp = __fdiv_rn(inter, denom) > IOU_TH;
                    bits = (bits & ~(1ull << jt)) | (((u64)supp) << jt);
                }
                if (c == iw) {
                    int bi = i & 63;
                    bits &= (bi == 63) ? 0ull : (~0ull << (bi + 1));
                }
                if (c == NWRD - 1) bits &= 0x0000FFFFFFFFFFFFull;
                g_supp[(size_t)i * NWRD + c] = bits;
            }
        }
    }
    // generation grid barrier (only on fallback path)
    __syncthreads();
    if (tid == 0) {
        __threadfence();
        u32 old = atomicAdd(&g_bar[5], 1u);
        u32 target = (old / NB + 1u) * NB;
        while (((volatile u32*)g_bar)[5] < target) __nanosleep(32);
    }
    __syncthreads();

    if (blockIdx.x != 0) return;

    int cnt0 = g_cnt;
    if (tid >= 32) return;
    for (int k = lane; k < cnt0; k += 32) s_sel[k] = g_klist[k];
    __syncwarp();

    u64 rem0 = 0, rem1 = 0, rem2 = 0;
    for (int k = 0; k < cnt0; k++) {
        const u64* row = &g_supp[(size_t)s_sel[k] * NWRD];
        rem0 |= __ldcg(&row[16 + lane]);
        rem1 |= __ldcg(&row[48 + lane]);
        if (lane < NWRD - 80) rem2 |= __ldcg(&row[80 + lane]);
    }
    u64 v0 = __ldcg(&g_valid[16 + lane]);
    u64 v1 = __ldcg(&g_valid[48 + lane]);
    u64 v2 = (lane < NWRD - 80) ? __ldcg(&g_valid[80 + lane]) : 0ull;

    int cnt = cnt0;
    for (int w = WW; w < NWRD && cnt < K_POST; w++) {
        int hi = (w - 16) >> 5, sl = (w - 16) & 31;
        u64 vv = hi == 0 ? v0 : (hi == 1 ? v1 : v2);
        u64 rr = hi == 0 ? rem0 : (hi == 1 ? rem1 : rem2);
        u64 cur = __shfl_sync(0xFFFFFFFFu, vv & ~rr, sl);
        while (cur && cnt < K_POST) {
            int i = w * 64 + (__ffsll((long long)cur) - 1);
            int iw = i >> 6;
            const u64* row = &g_supp[(size_t)i * NWRD];
            u64 r0 = (16 + lane >= iw) ? __ldcg(&row[16 + lane]) : 0ull;
            u64 r1 = (48 + lane >= iw) ? __ldcg(&row[48 + lane]) : 0ull;
            u64 r2 = (lane < NWRD - 80 && 80 + lane >= iw) ? __ldcg(&row[80 + lane]) : 0ull;
            rem0 |= r0; rem1 |= r1; rem2 |= r2;
            u64 rw = hi == 0 ? r0 : (hi == 1 ? r1 : r2);
            u64 roww = __shfl_sync(0xFFFFFFFFu, rw, sl);
            cur &= ~roww;
            cur &= ~(1ull << (i & 63));
            if (lane == 0) s_sel[cnt] = i;
            cnt++;
        }
    }
    __syncwarp();
    float4* out4 = reinterpret_cast<float4*>(out);
    for (int k = lane; k < K_POST; k += 32) {
        float4 b = make_float4(0.f, 0.f, 0.f, 0.f);
        if (k < cnt) b = __ldcg(&g_sbox[s_sel[k]]);
        out4[k] = b;
    }
}

extern "C" void kernel_launch(void* const* d_in, const int* in_sizes, int n_in,
                              void* d_out, int out_size) {
    const float2* cls = (const float2*)d_in[0];
    const float4* loc = (const float4*)d_in[1];
    const float4* anc = (const float4*)d_in[2];
    float* out = (float*)d_out;

    cudaFuncSetAttribute((const void*)k_D,
                         cudaFuncAttributeMaxDynamicSharedMemorySize, 131072);
    cudaFuncSetAttribute((const void*)k_F,
                         cudaFuncAttributeMaxDynamicSharedMemorySize, 131072);

    k_A<<<NB, TPB>>>(cls, loc, anc);
    k_B<<<1, 1024>>>();
    k_C<<<NB, TPB>>>();
    k_D<<<NB, TPB, 131072>>>();      // idempotent, run twice (timing probe)
    k_D<<<NB, TPB, 131072>>>();
    k_E<<<W1 * WW * 4 / TPB, TPB>>>();   // idempotent, run twice
    k_E<<<W1 * WW * 4 / TPB, TPB>>>();
    k_F<<<1, TPB, 131072>>>(out);    // idempotent, run twice
    k_F<<<1, TPB, 131072>>>(out);
    k_fall<<<NB, TPB>>>(out);
}

// round 10
// speedup vs baseline: 1.2512x; 1.2512x over previous
#include <cuda_runtime.h>
#include <cuda_bf16.h>
#include <cstdint>

#define NN      202500
#define K_PRE   6000
#define K_POST  300
#define NWRD    94
#define CAP     16384
#define NB      148
#define TPB     512
#define TOT     (NB*TPB)
#define IOU_TH  0.7f
#define MIN_SZ  0.016f
#define W1      1024            // window candidates
#define WW      16              // window words
#define NSTRIPR 12
#define FCOL    (NWRD - WW)

typedef unsigned long long u64;
typedef unsigned int u32;

__device__ u64    g_keys[NN];
__device__ float4 g_boxes[NN];
__device__ u32    g_hist[65536];     // zeroed by D-tail each launch (static init 0)
__device__ u32    g_bcnt[65536];
__device__ u32    g_nvalid;          // zeroed by D-tail each launch
__device__ u32    g_suf[65537];
__device__ u32    g_thresh;
__device__ u64    g_cand[CAP];
__device__ float4 g_sbox[K_PRE];
__device__ u64    g_valid[NWRD];
__device__ u64    g_wsupp[W1 * WW];
__device__ u64    g_supp[(size_t)K_PRE * NWRD];
__device__ u32    g_bar[8];          // generation counters (never reset)
__device__ int    g_fb;
__device__ int    g_cnt;
__device__ int    g_klist[K_POST];

// generation-based grid barrier, nanosleep backoff, replay-safe without reset
__device__ __forceinline__ void gridbar(int k) {
    __syncthreads();
    if (threadIdx.x == 0) {
        __threadfence();
        u32 old = atomicAdd(&g_bar[k], 1u);
        u32 target = (old / NB + 1u) * NB;
        while (((volatile u32*)g_bar)[k] < target) __nanosleep(32);
    }
    __syncthreads();
}

extern __shared__ u64 s_dyn[];   // 128KB

// =================== k_main: phases A-F ===================
__global__ void __launch_bounds__(TPB, 1)
k_main(const float2* __restrict__ cls,
       const float4* __restrict__ loc,
       const float4* __restrict__ anc,
       float* __restrict__ out) {
    __shared__ u32 s_wt[16];
    __shared__ int s_sel[K_POST];
    __shared__ int s_cnt;

    const int tid  = threadIdx.x;
    const int lane = tid & 31;
    const int wid  = tid >> 5;
    const int flat = blockIdx.x * TPB + tid;

    // ===== A: score + decode + key + histogram (valid-only!) =====
    if (flat < NWRD) g_valid[flat] = 0ull;
    u32 my_nvalid = 0;
    for (int n = flat; n < NN; n += TOT) {
        float2 c = cls[n];
        float m  = fmaxf(c.x, c.y);
        float e0 = expf(c.x - m);
        float e1 = expf(c.y - m);
        float s  = __fdiv_rn(e1, e0 + e1);

        float4 A = anc[n];
        float pcx = (A.z + A.x) * 0.5f;
        float pcy = (A.w + A.y) * 0.5f;
        float pw  = A.z - A.x;
        float ph  = A.w - A.y;

        float4 L = loc[n];
        float cx = L.x * pw + pcx;
        float cy = L.y * ph + pcy;
        float w  = expf(L.z) * pw;
        float h  = expf(L.w) * ph;

        float X0 = fminf(fmaxf(cx - w * 0.5f, 0.0f), 1.0f);
        float Y0 = fminf(fmaxf(cy - h * 0.5f, 0.0f), 1.0f);
        float X1 = fminf(fmaxf(cx + w * 0.5f, 0.0f), 1.0f);
        float Y1 = fminf(fmaxf(cy + h * 0.5f, 0.0f), 1.0f);

        bool valid = ((X1 - X0) >= MIN_SZ) && ((Y1 - Y0) >= MIN_SZ);
        float sm = valid ? s : -1.0f;

        u32 b  = __float_as_uint(sm);
        u32 fk = b ^ ((b >> 31) ? 0xFFFFFFFFu : 0x80000000u);

        g_keys[n]  = ((u64)fk << 32) | (u32)(~(u32)n);
        g_boxes[n] = make_float4(X0, Y0, X1, Y1);
        // CRITICAL: only valid boxes hit the histogram. Invalid boxes all share
        // one key (score -1.0) -> a single L2 address -> serialized atomics.
        if (valid) {
            atomicAdd(&g_hist[fk >> 16], 1u);
            my_nvalid++;
        }
    }
    // warp-aggregated valid count (one atomic per warp)
    {
        u32 v = my_nvalid;
        #pragma unroll
        for (int d = 16; d >= 1; d >>= 1) v += __shfl_down_sync(0xFFFFFFFFu, v, d);
        if (lane == 0 && v) atomicAdd(&g_nvalid, v);
    }
    gridbar(0);

    // ===== B: suffix sums + threshold (block 0) =====
    if (blockIdx.x == 0) {
        u32 target = g_nvalid;
        if (target > (u32)K_PRE) target = (u32)K_PRE;
        u32 ssum = 0;
        #pragma unroll 16
        for (int b = 0; b < 128; b++) ssum += g_hist[tid * 128 + b];
        u32 v = ssum;
        #pragma unroll
        for (int d = 1; d < 32; d <<= 1) {
            u32 o = __shfl_down_sync(0xFFFFFFFFu, v, d);
            if (lane < 32 - d) v += o;
        }
        if (lane == 0) s_wt[wid] = v;
        __syncthreads();
        if (tid < 16) {
            u32 t = s_wt[tid];
            #pragma unroll
            for (int d = 1; d < 16; d <<= 1) {
                u32 o = __shfl_down_sync(0x0000FFFFu, t, d);
                if (tid < 16 - d) t += o;
            }
            s_wt[tid] = t;
        }
        __syncthreads();
        u32 above = (wid < 15) ? s_wt[wid + 1] : 0u;
        u32 acc = (v + above) - ssum;
        if (tid == 0 && target == 0u) g_thresh = 0u;
        #pragma unroll 8
        for (int b = 127; b >= 0; b--) {
            int idx = tid * 128 + b;
            u32 prev = acc;
            acc += g_hist[idx];
            g_suf[idx] = acc;
            if (prev < target && acc >= target) g_thresh = (u32)idx;
        }
    }
    gridbar(1);

    // ===== C: compact valid candidates into per-bucket regions =====
    {
        u32 thr = g_thresh;
        for (int n = flat; n < NN; n += TOT) {
            u64 k = g_keys[n];
            u32 fk = (u32)(k >> 32);
            u32 b = fk >> 16;
            // candidates: bucket >= threshold AND valid (score >= 0)
            if (b >= thr && fk >= 0x80000000u) {
                u32 pos = g_suf[b + 1] + atomicAdd(&g_bcnt[b], 1u);
                if (pos < CAP) g_cand[pos] = k;
            }
        }
    }
    gridbar(2);

    // ===== D: rank via smem-staged keys; zero hist/bcnt/nvalid =====
    {
        u32 thr = g_thresh;
        u32 M = g_suf[thr]; if (M > CAP) M = CAP;
        for (u32 t = (u32)tid; t < M; t += TPB) s_dyn[t] = __ldcg(&g_cand[t]);
        __syncthreads();
        u32 i = (u32)flat;
        if (i < M) {
            u64 key = s_dyn[i];
            u32 b = (u32)(key >> 48);
            u32 start = g_suf[b + 1];
            u32 end   = g_suf[b]; if (end > M) end = M;
            u32 rank = start;
            #pragma unroll 8
            for (u32 j = start; j < end; j++) rank += (s_dyn[j] > key);
            if (rank < K_PRE) {
                u32 idx = ~(u32)key;
                g_sbox[rank] = g_boxes[idx];
                atomicOr(&g_valid[rank >> 6], 1ull << (rank & 63));  // all candidates valid
            }
        }
        for (u32 z = (u32)flat; z < 65536u; z += TOT) { g_hist[z] = 0u; g_bcnt[z] = 0u; }
        if (flat == 0) g_nvalid = 0u;
    }
    gridbar(3);

    // ===== E: window suppression matrix (1024 x 1024, quarter-word tasks) =====
    {
        float4* sb = (float4*)s_dyn;
        float*  sa = (float*)(sb + W1);
        __syncthreads();
        for (int t = tid; t < W1; t += TPB) {
            float4 b = __ldcg(&g_sbox[t]);
            sb[t] = b;
            sa[t] = (b.z - b.x) * (b.w - b.y);
        }
        __syncthreads();

        int task = flat;                    // 65536 quarter-word tasks
        int word = task >> 2;
        int i    = word >> 4;
        int c    = word & 15;
        int sub  = task & 3;
        u64 bits = 0ull;
        bool has = (task < W1 * WW * 4);
        if (has) {
            int iw = i >> 6;
            if (c >= iw) {
                float4 a = sb[i];
                float aarea = sa[i];
                int j0 = c * 64 + sub * 16;
                u32 lb = 0, ln = 0;
                #pragma unroll 16
                for (int jt = 0; jt < 16; jt++) {
                    float4 b = sb[j0 + jt];
                    float wx = fmaxf(fminf(a.z, b.z) - fmaxf(a.x, b.x), 0.0f);
                    float wy = fmaxf(fminf(a.w, b.w) - fmaxf(a.y, b.y), 0.0f);
                    float inter = wx * wy;
                    float denom = ((aarea + sa[j0 + jt]) - inter) + 1e-12f;
                    float m = IOU_TH * denom;
                    lb |= ((u32)(inter > m)) << jt;
                    ln |= ((u32)(fabsf(inter - m) <= 2e-6f * denom)) << jt;
                }
                while (ln) {   // rare exact fixup with reference division
                    int jt = __ffs(ln) - 1; ln &= ln - 1;
                    float4 b = sb[j0 + jt];
                    float wx = fmaxf(fminf(a.z, b.z) - fmaxf(a.x, b.x), 0.0f);
                    float wy = fmaxf(fminf(a.w, b.w) - fmaxf(a.y, b.y), 0.0f);
                    float inter = wx * wy;
                    float denom = ((aarea + sa[j0 + jt]) - inter) + 1e-12f;
                    bool supp = __fdiv_rn(inter, denom) > IOU_TH;
                    lb = (lb & ~(1u << jt)) | (((u32)supp) << jt);
                }
                bits = ((u64)lb) << (16 * sub);
            }
        }
        bits |= __shfl_xor_sync(0xFFFFFFFFu, bits, 1);
        bits |= __shfl_xor_sync(0xFFFFFFFFu, bits, 2);
        if (has && sub == 0) {
            int iw = i >> 6;
            if (c == iw) {
                int bi = i & 63;
                bits &= (bi == 63) ? 0ull : (~0ull << (bi + 1));   // j > i
            }
            g_wsupp[word] = bits;
        }
    }
    gridbar(4);

    // ===== F: flattened live-vector scan (block 0, <=300+stage iterations) =====
    if (blockIdx.x != 0) return;
    {
        u64* sc = s_dyn;
        __syncthreads();
        for (int t = tid; t < W1 * WW; t += TPB) sc[t] = __ldcg(&g_wsupp[t]);
        __syncthreads();
        if (tid < 32) {
            u64 live = (lane < WW) ? __ldcg(&g_valid[lane]) : 0ull;
            int cnt = 0;
            while (cnt < K_POST) {
                u32 nz = __ballot_sync(0xFFFFFFFFu, live != 0ull);
                if (!nz) break;
                int w = __ffs(nz) - 1;
                u64 wv = __shfl_sync(0xFFFFFFFFu, live, w);
                int b = __ffsll((long long)wv) - 1;
                int i = (w << 6) + b;
                u64 row = (lane < WW) ? sc[i * WW + lane] : 0ull;
                live &= ~row;
                if (lane == w) live &= ~(1ull << b);
                if (lane == 0) s_sel[cnt] = i;
                cnt++;
            }
            if (lane == 0) s_cnt = cnt;
        }
        __syncthreads();
        int cnt = s_cnt;
        for (int k = tid; k < cnt; k += TPB) g_klist[k] = s_sel[k];
        if (cnt >= K_POST) {
            float4* out4 = reinterpret_cast<float4*>(out);
            for (int k = tid; k < K_POST; k += TPB)
                out4[k] = __ldcg(&g_sbox[s_sel[k]]);
        }
        if (tid == 0) { g_cnt = cnt; g_fb = (cnt >= K_POST) ? 0 : 1; }
    }
}

// =================== k_fall: continuation (guarded) ===================
__global__ void __launch_bounds__(TPB, 1)
k_fall(float* __restrict__ out) {
    __shared__ float4 s_cb[64];
    __shared__ float  s_ca[64];
    __shared__ int    s_sel[K_POST];

    const int tid  = threadIdx.x;
    const int lane = tid & 31;

    if (g_fb == 0) return;

    // full suppression matrix, columns 16..93 only
    for (int s = blockIdx.x; s < FCOL * NSTRIPR; s += NB) {
        int c = WW + s % FCOL;
        int r = s / FCOL;
        if (c * 64 + 63 < r * TPB) continue;
        __syncthreads();
        if (tid < 64) {
            int j = c * 64 + tid;
            float4 bb = (j < K_PRE) ? __ldcg(&g_sbox[j]) : make_float4(0.f, 0.f, 0.f, 0.f);
            s_cb[tid] = bb;
            s_ca[tid] = (bb.z - bb.x) * (bb.w - bb.y);
        }
        __syncthreads();
        int i = r * TPB + tid;
        if (i < K_PRE) {
            int iw = i >> 6;
            if (c >= iw) {
                float4 a = __ldcg(&g_sbox[i]);
                float aarea = (a.z - a.x) * (a.w - a.y);
                u64 bits = 0ull, near_ = 0ull;
                #pragma unroll 8
                for (int jt = 0; jt < 64; jt++) {
                    float4 b = s_cb[jt];
                    float wx = fmaxf(fminf(a.z, b.z) - fmaxf(a.x, b.x), 0.0f);
                    float wy = fmaxf(fminf(a.w, b.w) - fmaxf(a.y, b.y), 0.0f);
                    float inter = wx * wy;
                    float denom = ((aarea + s_ca[jt]) - inter) + 1e-12f;
                    float m = IOU_TH * denom;
                    bits  |= ((u64)(inter > m)) << jt;
                    near_ |= ((u64)(fabsf(inter - m) <= 2e-6f * denom)) << jt;
                }
                while (near_) {
                    int jt = __ffsll((long long)near_) - 1; near_ &= near_ - 1;
                    float4 b = s_cb[jt];
                    float wx = fmaxf(fminf(a.z, b.z) - fmaxf(a.x, b.x), 0.0f);
                    float wy = fmaxf(fminf(a.w, b.w) - fmaxf(a.y, b.y), 0.0f);
                    float inter = wx * wy;
                    float denom = ((aarea + s_ca[jt]) - inter) + 1e-12f;
                    bool supp = __fdiv_rn(inter, denom) > IOU_TH;
                    bits = (bits & ~(1ull << jt)) | (((u64)supp) << jt);
                }
                if (c == iw) {
                    int bi = i & 63;
                    bits &= (bi == 63) ? 0ull : (~0ull << (bi + 1));
                }
                if (c == NWRD - 1) bits &= 0x0000FFFFFFFFFFFFull;
                g_supp[(size_t)i * NWRD + c] = bits;
            }
        }
    }
    // generation grid barrier (fallback path only, slot 5)
    __syncthreads();
    if (tid == 0) {
        __threadfence();
        u32 old = atomicAdd(&g_bar[5], 1u);
        u32 target = (old / NB + 1u) * NB;
        while (((volatile u32*)g_bar)[5] < target) __nanosleep(32);
    }
    __syncthreads();

    if (blockIdx.x != 0) return;

    int cnt0 = g_cnt;
    if (tid >= 32) return;
    for (int k = lane; k < cnt0; k += 32) s_sel[k] = g_klist[k];
    __syncwarp();

    u64 rem0 = 0, rem1 = 0, rem2 = 0;
    for (int k = 0; k < cnt0; k++) {
        const u64* row = &g_supp[(size_t)s_sel[k] * NWRD];
        rem0 |= __ldcg(&row[16 + lane]);
        rem1 |= __ldcg(&row[48 + lane]);
        if (lane < NWRD - 80) rem2 |= __ldcg(&row[80 + lane]);
    }
    u64 v0 = __ldcg(&g_valid[16 + lane]);
    u64 v1 = __ldcg(&g_valid[48 + lane]);
    u64 v2 = (lane < NWRD - 80) ? __ldcg(&g_valid[80 + lane]) : 0ull;

    int cnt = cnt0;
    for (int w = WW; w < NWRD && cnt < K_POST; w++) {
        int hi = (w - 16) >> 5, sl = (w - 16) & 31;
        u64 vv = hi == 0 ? v0 : (hi == 1 ? v1 : v2);
        u64 rr = hi == 0 ? rem0 : (hi == 1 ? rem1 : rem2);
        u64 cur = __shfl_sync(0xFFFFFFFFu, vv & ~rr, sl);
        while (cur && cnt < K_POST) {
            int i = w * 64 + (__ffsll((long long)cur) - 1);
            int iw = i >> 6;
            const u64* row = &g_supp[(size_t)i * NWRD];
            u64 r0 = (16 + lane >= iw) ? __ldcg(&row[16 + lane]) : 0ull;
            u64 r1 = (48 + lane >= iw) ? __ldcg(&row[48 + lane]) : 0ull;
            u64 r2 = (lane < NWRD - 80 && 80 + lane >= iw) ? __ldcg(&row[80 + lane]) : 0ull;
            rem0 |= r0; rem1 |= r1; rem2 |= r2;
            u64 rw = hi == 0 ? r0 : (hi == 1 ? r1 : r2);
            u64 roww = __shfl_sync(0xFFFFFFFFu, rw, sl);
            cur &= ~roww;
            cur &= ~(1ull << (i & 63));
            if (lane == 0) s_sel[cnt] = i;
            cnt++;
        }
    }
    __syncwarp();
    float4* out4 = reinterpret_cast<float4*>(out);
    for (int k = lane; k < K_POST; k += 32) {
        float4 b = make_float4(0.f, 0.f, 0.f, 0.f);
        if (k < cnt) b = __ldcg(&g_sbox[s_sel[k]]);
        out4[k] = b;
    }
}

extern "C" void kernel_launch(void* const* d_in, const int* in_sizes, int n_in,
                              void* d_out, int out_size) {
    const float2* cls = (const float2*)d_in[0];
    const float4* loc = (const float4*)d_in[1];
    const float4* anc = (const float4*)d_in[2];
    float* out = (float*)d_out;

    cudaFuncSetAttribute((const void*)k_main,
                         cudaFuncAttributeMaxDynamicSharedMemorySize, 131072);

    k_main<<<NB, TPB, 131072>>>(cls, loc, anc, out);
    k_fall<<<NB, TPB>>>(out);
}

// round 11
// speedup vs baseline: 3.4655x; 2.7697x over previous
#include <cuda_runtime.h>
#include <cuda_bf16.h>
#include <cstdint>

#define NN      202500
#define K_PRE   6000
#define K_POST  300
#define NWRD    94
#define CAP     16384
#define NB      148
#define TPB     512
#define TOT     (NB*TPB)
#define IOU_TH  0.7f
#define MIN_SZ  0.016f
#define W1      1024            // window candidates
#define WW      16              // window words
#define NSTRIPR 12
#define FCOL    (NWRD - WW)
#define NREP    8               // histogram replicas

typedef unsigned long long u64;
typedef unsigned int u32;

__device__ u64    g_keys[NN];
__device__ float4 g_boxes[NN];
__device__ u32    g_histr[NREP * 65536]; // replicated histogram (zeroed by D-tail)
__device__ u32    g_hist[65536];         // merged (overwritten by B1 each launch)
__device__ u32    g_c2[1024];            // chunk sums (zeroed by D-tail)
__device__ u32    g_s2[1024];            // chunk exclusive-above suffix
__device__ u32    g_bcnt[65536];
__device__ u32    g_nvalid;
__device__ u32    g_suf[65537];          // [65536] stays 0 forever
__device__ u32    g_thresh;
__device__ u64    g_cand[CAP];
__device__ float4 g_sbox[K_PRE];
__device__ u64    g_valid[NWRD];
__device__ u64    g_wsupp[W1 * WW];
__device__ u64    g_supp[(size_t)K_PRE * NWRD];
__device__ u32    g_bar[16];             // generation counters (never reset)
__device__ int    g_fb;

__device__ __forceinline__ void gridbar(int k) {
    __syncthreads();
    if (threadIdx.x == 0) {
        __threadfence();
        u32 old = atomicAdd(&g_bar[k], 1u);
        u32 target = (old / NB + 1u) * NB;
        while (((volatile u32*)g_bar)[k] < target) __nanosleep(32);
    }
    __syncthreads();
}

extern __shared__ u64 s_dyn[];   // 128KB

__global__ void __launch_bounds__(TPB, 1)
k_all(const float2* __restrict__ cls,
      const float4* __restrict__ loc,
      const float4* __restrict__ anc,
      float* __restrict__ out) {
    __shared__ u32    s_wt[16];
    __shared__ int    s_sel[K_POST];
    __shared__ int    s_cnt;
    __shared__ float4 s_cb[64];
    __shared__ float  s_ca[64];

    const int tid  = threadIdx.x;
    const int lane = tid & 31;
    const int wid  = tid >> 5;
    const int flat = blockIdx.x * TPB + tid;
    const u32 repbase = (u32)(blockIdx.x & (NREP - 1)) << 16;

    // ===== A: score + decode + key + replicated histogram (valid-only) =====
    if (flat < NWRD) g_valid[flat] = 0ull;
    u32 my_nvalid = 0;
    for (int n = flat; n < NN; n += TOT) {
        float2 c = cls[n];
        float m  = fmaxf(c.x, c.y);
        float e0 = expf(c.x - m);
        float e1 = expf(c.y - m);
        float s  = __fdiv_rn(e1, e0 + e1);

        float4 A = anc[n];
        float pcx = (A.z + A.x) * 0.5f;
        float pcy = (A.w + A.y) * 0.5f;
        float pw  = A.z - A.x;
        float ph  = A.w - A.y;

        float4 L = loc[n];
        float cx = L.x * pw + pcx;
        float cy = L.y * ph + pcy;
        float w  = expf(L.z) * pw;
        float h  = expf(L.w) * ph;

        float X0 = fminf(fmaxf(cx - w * 0.5f, 0.0f), 1.0f);
        float Y0 = fminf(fmaxf(cy - h * 0.5f, 0.0f), 1.0f);
        float X1 = fminf(fmaxf(cx + w * 0.5f, 0.0f), 1.0f);
        float Y1 = fminf(fmaxf(cy + h * 0.5f, 0.0f), 1.0f);

        bool valid = ((X1 - X0) >= MIN_SZ) && ((Y1 - Y0) >= MIN_SZ);
        float sm = valid ? s : -1.0f;

        u32 b  = __float_as_uint(sm);
        u32 fk = b ^ ((b >> 31) ? 0xFFFFFFFFu : 0x80000000u);

        g_keys[n]  = ((u64)fk << 32) | (u32)(~(u32)n);
        g_boxes[n] = make_float4(X0, Y0, X1, Y1);
        if (valid) {
            atomicAdd(&g_histr[repbase + (fk >> 16)], 1u);
            my_nvalid++;
        }
    }
    {
        u32 v = my_nvalid;
        #pragma unroll
        for (int d = 16; d >= 1; d >>= 1) v += __shfl_down_sync(0xFFFFFFFFu, v, d);
        if (lane == 0 && v) atomicAdd(&g_nvalid, v);
    }
    gridbar(0);

    // ===== B1: merge replicas + chunk sums (all blocks) =====
    if (flat < 65536) {
        u32 h = 0;
        #pragma unroll
        for (int r = 0; r < NREP; r++) h += g_histr[(r << 16) + flat];
        g_hist[flat] = h;
        if (h) atomicAdd(&g_c2[flat >> 6], h);
    }
    gridbar(1);

    // ===== B2: suffix over 1024 chunks (block 0) =====
    if (blockIdx.x == 0) {
        u32 cA = g_c2[2 * tid];
        u32 cB = g_c2[2 * tid + 1];
        u32 pairv = cA + cB;
        u32 v = pairv;
        #pragma unroll
        for (int d = 1; d < 32; d <<= 1) {
            u32 o = __shfl_down_sync(0xFFFFFFFFu, v, d);
            if (lane < 32 - d) v += o;
        }
        if (lane == 0) s_wt[wid] = v;
        __syncthreads();
        if (tid < 16) {
            u32 t = s_wt[tid];
            #pragma unroll
            for (int d = 1; d < 16; d <<= 1) {
                u32 o = __shfl_down_sync(0x0000FFFFu, t, d);
                if (tid < 16 - d) t += o;
            }
            s_wt[tid] = t;
        }
        __syncthreads();
        u32 above = (wid < 15) ? s_wt[wid + 1] : 0u;
        u32 pairs_above = (v + above) - pairv;   // pairs strictly above mine
        g_s2[2 * tid + 1] = pairs_above;         // chunk 2t+1 exclusive-above
        g_s2[2 * tid]     = pairs_above + cB;    // chunk 2t exclusive-above
        if (tid == 0) {
            u32 tgt = g_nvalid;
            if (tgt == 0u) g_thresh = 0u;        // degenerate: no valid boxes
        }
    }
    gridbar(2);

    // ===== B3: per-bucket suffix within chunks (1024 warps grid-wide) =====
    {
        int W = flat >> 5;
        if (W < 1024) {
            u32 tgt = g_nvalid;
            if (tgt > (u32)K_PRE) tgt = (u32)K_PRE;
            int b_hi = (W << 6) + 2 * lane + 1;
            int b_lo = (W << 6) + 2 * lane;
            u32 h_hi = g_hist[b_hi];
            u32 h_lo = g_hist[b_lo];
            u32 pairv = h_hi + h_lo;
            u32 v = pairv;
            #pragma unroll
            for (int d = 1; d < 32; d <<= 1) {
                u32 o = __shfl_down_sync(0xFFFFFFFFu, v, d);
                if (lane < 32 - d) v += o;
            }
            u32 above = g_s2[W] + (v - pairv);   // strictly above bucket b_hi
            u32 incl_hi = above + h_hi;
            u32 incl_lo = incl_hi + h_lo;
            g_suf[b_hi] = incl_hi;
            g_suf[b_lo] = incl_lo;
            if (tgt) {
                if (above < tgt && incl_hi >= tgt) g_thresh = (u32)b_hi;
                if (incl_hi < tgt && incl_lo >= tgt) g_thresh = (u32)b_lo;
            }
        }
    }
    gridbar(3);

    // ===== C: compact valid candidates into per-bucket regions =====
    {
        u32 thr = g_thresh;
        for (int n = flat; n < NN; n += TOT) {
            u64 k = g_keys[n];
            u32 fk = (u32)(k >> 32);
            u32 b = fk >> 16;
            if (b >= thr && fk >= 0x80000000u) {
                u32 pos = g_suf[b + 1] + atomicAdd(&g_bcnt[b], 1u);
                if (pos < CAP) g_cand[pos] = k;
            }
        }
    }
    gridbar(4);

    // ===== D: rank via smem-staged keys; zero scratch =====
    {
        u32 thr = g_thresh;
        u32 M = g_suf[thr]; if (M > CAP) M = CAP;
        for (u32 t = (u32)tid; t < M; t += TPB) s_dyn[t] = __ldcg(&g_cand[t]);
        __syncthreads();
        u32 i = (u32)flat;
        if (i < M) {
            u64 key = s_dyn[i];
            u32 b = (u32)(key >> 48);
            u32 start = g_suf[b + 1];
            u32 end   = g_suf[b]; if (end > M) end = M;
            u32 rank = start;
            #pragma unroll 8
            for (u32 j = start; j < end; j++) rank += (s_dyn[j] > key);
            if (rank < K_PRE) {
                u32 idx = ~(u32)key;
                g_sbox[rank] = g_boxes[idx];
                atomicOr(&g_valid[rank >> 6], 1ull << (rank & 63));
            }
        }
        for (u32 z = (u32)flat; z < (u32)(NREP * 65536); z += TOT) g_histr[z] = 0u;
        for (u32 z = (u32)flat; z < 65536u; z += TOT) g_bcnt[z] = 0u;
        if (flat < 1024) g_c2[flat] = 0u;
        if (flat == 0) g_nvalid = 0u;
    }
    gridbar(5);

    // ===== E: window suppression matrix (1024 x 1024) =====
    {
        float4* sb = (float4*)s_dyn;
        float*  sa = (float*)(sb + W1);
        __syncthreads();
        for (int t = tid; t < W1; t += TPB) {
            float4 b = __ldcg(&g_sbox[t]);
            sb[t] = b;
            sa[t] = (b.z - b.x) * (b.w - b.y);
        }
        __syncthreads();

        int task = flat;
        int word = task >> 2;
        int i    = word >> 4;
        int c    = word & 15;
        int sub  = task & 3;
        u64 bits = 0ull;
        bool has = (task < W1 * WW * 4);
        if (has) {
            int iw = i >> 6;
            if (c >= iw) {
                float4 a = sb[i];
                float aarea = sa[i];
                int j0 = c * 64 + sub * 16;
                u32 lb = 0, ln = 0;
                #pragma unroll 16
                for (int jt = 0; jt < 16; jt++) {
                    float4 b = sb[j0 + jt];
                    float wx = fmaxf(fminf(a.z, b.z) - fmaxf(a.x, b.x), 0.0f);
                    float wy = fmaxf(fminf(a.w, b.w) - fmaxf(a.y, b.y), 0.0f);
                    float inter = wx * wy;
                    float denom = ((aarea + sa[j0 + jt]) - inter) + 1e-12f;
                    float m = IOU_TH * denom;
                    lb |= ((u32)(inter > m)) << jt;
                    ln |= ((u32)(fabsf(inter - m) <= 2e-6f * denom)) << jt;
                }
                while (ln) {   // rare exact fixup with reference division
                    int jt = __ffs(ln) - 1; ln &= ln - 1;
                    float4 b = sb[j0 + jt];
                    float wx = fmaxf(fminf(a.z, b.z) - fmaxf(a.x, b.x), 0.0f);
                    float wy = fmaxf(fminf(a.w, b.w) - fmaxf(a.y, b.y), 0.0f);
                    float inter = wx * wy;
                    float denom = ((aarea + sa[j0 + jt]) - inter) + 1e-12f;
                    bool supp = __fdiv_rn(inter, denom) > IOU_TH;
                    lb = (lb & ~(1u << jt)) | (((u32)supp) << jt);
                }
                bits = ((u64)lb) << (16 * sub);
            }
        }
        bits |= __shfl_xor_sync(0xFFFFFFFFu, bits, 1);
        bits |= __shfl_xor_sync(0xFFFFFFFFu, bits, 2);
        if (has && sub == 0) {
            int iw = i >> 6;
            if (c == iw) {
                int bi = i & 63;
                bits &= (bi == 63) ? 0ull : (~0ull << (bi + 1));
            }
            g_wsupp[word] = bits;
        }
    }
    gridbar(6);

    // ===== F: flattened live-vector scan (block 0) =====
    if (blockIdx.x == 0) {
        u64* sc = s_dyn;
        __syncthreads();
        for (int t = tid; t < W1 * WW; t += TPB) sc[t] = __ldcg(&g_wsupp[t]);
        __syncthreads();
        if (tid < 32) {
            u64 live = (lane < WW) ? __ldcg(&g_valid[lane]) : 0ull;
            int cnt = 0;
            while (cnt < K_POST) {
                u32 nz = __ballot_sync(0xFFFFFFFFu, live != 0ull);
                if (!nz) break;
                int w = __ffs(nz) - 1;
                u64 wv = __shfl_sync(0xFFFFFFFFu, live, w);
                int b = __ffsll((long long)wv) - 1;
                int i = (w << 6) + b;
                u64 row = (lane < WW) ? sc[i * WW + lane] : 0ull;
                live &= ~row;
                if (lane == w) live &= ~(1ull << b);
                if (lane == 0) s_sel[cnt] = i;
                cnt++;
            }
            if (lane == 0) s_cnt = cnt;
        }
        __syncthreads();
        int cnt = s_cnt;
        if (cnt >= K_POST) {
            float4* out4 = reinterpret_cast<float4*>(out);
            for (int k = tid; k < K_POST; k += TPB)
                out4[k] = __ldcg(&g_sbox[s_sel[k]]);
        }
        if (tid == 0) g_fb = (cnt >= K_POST) ? 0 : 1;
    }
    gridbar(7);

    if (((volatile int*)&g_fb)[0] == 0) return;

    // ===== Fallback: full matrix cols 16..93 + continuation scan =====
    for (int s = blockIdx.x; s < FCOL * NSTRIPR; s += NB) {
        int c = WW + s % FCOL;
        int r = s / FCOL;
        if (c * 64 + 63 < r * TPB) continue;
        __syncthreads();
        if (tid < 64) {
            int j = c * 64 + tid;
            float4 bb = (j < K_PRE) ? __ldcg(&g_sbox[j]) : make_float4(0.f, 0.f, 0.f, 0.f);
            s_cb[tid] = bb;
            s_ca[tid] = (bb.z - bb.x) * (bb.w - bb.y);
        }
        __syncthreads();
        int i = r * TPB + tid;
        if (i < K_PRE) {
            int iw = i >> 6;
            if (c >= iw) {
                float4 a = __ldcg(&g_sbox[i]);
                float aarea = (a.z - a.x) * (a.w - a.y);
                u64 bits = 0ull, near_ = 0ull;
                #pragma unroll 8
                for (int jt = 0; jt < 64; jt++) {
                    float4 b = s_cb[jt];
                    float wx = fmaxf(fminf(a.z, b.z) - fmaxf(a.x, b.x), 0.0f);
                    float wy = fmaxf(fminf(a.w, b.w) - fmaxf(a.y, b.y), 0.0f);
                    float inter = wx * wy;
                    float denom = ((aarea + s_ca[jt]) - inter) + 1e-12f;
                    float m = IOU_TH * denom;
                    bits  |= ((u64)(inter > m)) << jt;
                    near_ |= ((u64)(fabsf(inter - m) <= 2e-6f * denom)) << jt;
                }
                while (near_) {
                    int jt = __ffsll((long long)near_) - 1; near_ &= near_ - 1;
                    float4 b = s_cb[jt];
                    float wx = fmaxf(fminf(a.z, b.z) - fmaxf(a.x, b.x), 0.0f);
                    float wy = fmaxf(fminf(a.w, b.w) - fmaxf(a.y, b.y), 0.0f);
                    float inter = wx * wy;
                    float denom = ((aarea + s_ca[jt]) - inter) + 1e-12f;
                    bool supp = __fdiv_rn(inter, denom) > IOU_TH;
                    bits = (bits & ~(1ull << jt)) | (((u64)supp) << jt);
                }
                if (c == iw) {
                    int bi = i & 63;
                    bits &= (bi == 63) ? 0ull : (~0ull << (bi + 1));
                }
                if (c == NWRD - 1) bits &= 0x0000FFFFFFFFFFFFull;
                g_supp[(size_t)i * NWRD + c] = bits;
            }
        }
    }
    gridbar(8);

    if (blockIdx.x != 0) return;
    {
        int cnt0 = s_cnt;                 // persists in block 0's shared memory
        if (tid >= 32) return;

        u64 rem0 = 0, rem1 = 0, rem2 = 0;
        for (int k = 0; k < cnt0; k++) {
            const u64* row = &g_supp[(size_t)s_sel[k] * NWRD];
            rem0 |= __ldcg(&row[16 + lane]);
            rem1 |= __ldcg(&row[48 + lane]);
            if (lane < NWRD - 80) rem2 |= __ldcg(&row[80 + lane]);
        }
        u64 v0 = __ldcg(&g_valid[16 + lane]);
        u64 v1 = __ldcg(&g_valid[48 + lane]);
        u64 v2 = (lane < NWRD - 80) ? __ldcg(&g_valid[80 + lane]) : 0ull;

        int cnt = cnt0;
        for (int w = WW; w < NWRD && cnt < K_POST; w++) {
            int hi = (w - 16) >> 5, sl = (w - 16) & 31;
            u64 vv = hi == 0 ? v0 : (hi == 1 ? v1 : v2);
            u64 rr = hi == 0 ? rem0 : (hi == 1 ? rem1 : rem2);
            u64 cur = __shfl_sync(0xFFFFFFFFu, vv & ~rr, sl);
            while (cur && cnt < K_POST) {
                int i = w * 64 + (__ffsll((long long)cur) - 1);
                int iw = i >> 6;
                const u64* row = &g_supp[(size_t)i * NWRD];
                u64 r0 = (16 + lane >= iw) ? __ldcg(&row[16 + lane]) : 0ull;
                u64 r1 = (48 + lane >= iw) ? __ldcg(&row[48 + lane]) : 0ull;
                u64 r2 = (lane < NWRD - 80 && 80 + lane >= iw) ? __ldcg(&row[80 + lane]) : 0ull;
                rem0 |= r0; rem1 |= r1; rem2 |= r2;
                u64 rw = hi == 0 ? r0 : (hi == 1 ? r1 : r2);
                u64 roww = __shfl_sync(0xFFFFFFFFu, rw, sl);
                cur &= ~roww;
                cur &= ~(1ull << (i & 63));
                if (lane == 0) s_sel[cnt] = i;
                cnt++;
            }
        }
        __syncwarp();
        float4* out4 = reinterpret_cast<float4*>(out);
        for (int k = lane; k < K_POST; k += 32) {
            float4 b = make_float4(0.f, 0.f, 0.f, 0.f);
            if (k < cnt) b = __ldcg(&g_sbox[s_sel[k]]);
            out4[k] = b;
        }
    }
}

extern "C" void kernel_launch(void* const* d_in, const int* in_sizes, int n_in,
                              void* d_out, int out_size) {
    const float2* cls = (const float2*)d_in[0];
    const float4* loc = (const float4*)d_in[1];
    const float4* anc = (const float4*)d_in[2];
    float* out = (float*)d_out;

    cudaFuncSetAttribute((const void*)k_all,
                         cudaFuncAttributeMaxDynamicSharedMemorySize, 131072);

    k_all<<<NB, TPB, 131072>>>(cls, loc, anc, out);
}